// round 2
// baseline (speedup 1.0000x reference)
#include <cuda_runtime.h>
#include <math.h>

#define NN    50000
#define NE    320000
#define D_IN  128
#define D_OUT 256
#define D_HID 512

// ---------------- scratch (static device globals; no allocation) ----------------
__device__ float  g_X1 [(size_t)NN * D_IN];
__device__ float  g_XN [(size_t)NN * D_OUT];
__device__ float  g_H  [(size_t)NN * D_OUT];
__device__ float  g_T  [(size_t)NN * D_HID];
__device__ float  g_U  [(size_t)NN * D_OUT];
__device__ float  g_RE1[(size_t)NN * D_IN];
__device__ float  g_RE2[(size_t)NN * D_IN];
__device__ double g_sum[D_HID];
__device__ double g_sq [D_HID];
__device__ float  g_mean[D_HID];
__device__ float  g_rstd[D_HID];
__device__ double g_acc[8]; // [0]=sum1 [1]=cnt1 [2]=sum2 [3]=cnt2 [4]=cl_sum

// dtype-detection flags + counters
__device__ int g_mask_mode;   // 0 = uint8, 1 = int32, 2 = float32
__device__ int g_ei_i64;      // 0 = int32, 1 = int64
__device__ int g_cnt[8];      // scratch counters

// ---------------- dtype detection ----------------
__global__ void k_zero_cnt() { if (threadIdx.x < 8) g_cnt[threadIdx.x] = 0; }

// Inspect only the first NN bytes of the mask buffer (in-bounds for every dtype)
// and the first 100000 int32 slots of the edge buffer (in-bounds for i32 & i64).
__global__ void k_detect(const unsigned char* __restrict__ mbytes,
                         const int* __restrict__ eints) {
    int i  = blockIdx.x * blockDim.x + threadIdx.x;
    int st = gridDim.x * blockDim.x;
    int c1 = 0, c3 = 0, ez = 0;
    for (int j = i; j < NN; j += st) {
        unsigned char v = mbytes[j];
        if (v && (j & 3) == 1) c1++;          // uint8 mask has ones at mod-1 bytes
        if (v && (j & 3) == 3) c3++;          // f32 mask (1.0f) has 0x3f at mod-3
    }
    for (int j = i; j < 100000; j += st)
        if ((j & 1) && eints[j] == 0) ez++;   // int64 edges: odd slots are zero hi-words
    atomicAdd(&g_cnt[0], c1);
    atomicAdd(&g_cnt[1], c3);
    atomicAdd(&g_cnt[2], ez);
}

__global__ void k_detect_fin() {
    if (threadIdx.x == 0) {
        if      (g_cnt[1] > 1000) g_mask_mode = 2;   // float32
        else if (g_cnt[0] > 1000) g_mask_mode = 0;   // uint8
        else                      g_mask_mode = 1;   // int32
        g_ei_i64 = (g_cnt[2] > 25000) ? 1 : 0;
    }
}

__device__ __forceinline__ bool mask_at(const void* __restrict__ m, int n) {
    int mode = g_mask_mode;
    if (mode == 0) return ((const unsigned char*)m)[n] != 0;
    if (mode == 1) return ((const int*)m)[n] != 0;
    return ((const float*)m)[n] != 0.f;
}

__device__ __forceinline__ int ei_at(const void* __restrict__ ei, long idx) {
    return g_ei_i64 ? (int)((const long long*)ei)[idx] : ((const int*)ei)[idx];
}

// ---------------- tiny utility kernels ----------------
__global__ void k_zero_acc() {
    if (threadIdx.x < 8) g_acc[threadIdx.x] = 0.0;
}

__global__ void k_zero_stats(int C) {
    int c = threadIdx.x;
    if (c < C) { g_sum[c] = 0.0; g_sq[c] = 0.0; }
}

// out[i] = mask[node] ? 0 : in[i]   (dshift = log2(D)); works in-place
__global__ void k_mask(const float* __restrict__ in, const void* __restrict__ m,
                       float* __restrict__ out, int dshift, long total) {
    long i  = blockIdx.x * (long)blockDim.x + threadIdx.x;
    long st = (long)gridDim.x * blockDim.x;
    for (; i < total; i += st) {
        int node = (int)(i >> dshift);
        out[i] = mask_at(m, node) ? 0.f : in[i];
    }
}

__global__ void k_copy4(const float4* __restrict__ src, float4* __restrict__ dst, long n4) {
    long i  = blockIdx.x * (long)blockDim.x + threadIdx.x;
    long st = (long)gridDim.x * blockDim.x;
    for (; i < n4; i += st) dst[i] = src[i];
}

// ---------------- edge scatter: h[dst] += xn[src], one warp per edge ----------------
__global__ void k_scatter(const float* __restrict__ xn, float* __restrict__ h,
                          const void* __restrict__ ei, int D) {
    int gtid = blockIdx.x * blockDim.x + threadIdx.x;
    int warp = gtid >> 5, lane = gtid & 31;
    int nw   = (gridDim.x * blockDim.x) >> 5;
    for (int e = warp; e < NE; e += nw) {
        int s = ei_at(ei, e);
        int d = ei_at(ei, (long)NE + e);
        const float* sp = xn + (size_t)s * D;
        float*       dp = h  + (size_t)d * D;
        for (int c = lane; c < D; c += 32)
            atomicAdd(&dp[c], __ldg(&sp[c]));
    }
}

// ---------------- SGEMM: C[MxN] = A[MxK] @ B[KxN], row-major fp32 ----------------
// 128x128 tile, BK=8, 256 threads, 8x8 per-thread microtile.
// Requires: K % 8 == 0, N % 128 == 0 (true for all 6 GEMM shapes here); M ragged.
__global__ void __launch_bounds__(256)
k_sgemm(const float* __restrict__ A, const float* __restrict__ B,
        float* __restrict__ C, int M, int K, int N) {
    __shared__ float As[8][128];
    __shared__ float Bs[8][128];
    const int tid  = threadIdx.x;
    const int brow = blockIdx.y * 128;
    const int bcol = blockIdx.x * 128;
    const int tr   = (tid >> 4) << 3;
    const int tc   = (tid & 15) << 3;
    const int aRow = tid >> 1;
    const int aCol = (tid & 1) << 2;
    const int bRow = tid >> 5;
    const int bCol = (tid & 31) << 2;
    const int gra  = brow + aRow;

    float acc[8][8];
    #pragma unroll
    for (int i = 0; i < 8; i++)
        #pragma unroll
        for (int j = 0; j < 8; j++) acc[i][j] = 0.f;

    for (int k0 = 0; k0 < K; k0 += 8) {
        float4 a4 = (gra < M) ? *(const float4*)(A + (size_t)gra * K + k0 + aCol)
                              : make_float4(0.f, 0.f, 0.f, 0.f);
        As[aCol + 0][aRow] = a4.x;
        As[aCol + 1][aRow] = a4.y;
        As[aCol + 2][aRow] = a4.z;
        As[aCol + 3][aRow] = a4.w;
        *(float4*)(&Bs[bRow][bCol]) =
            *(const float4*)(B + (size_t)(k0 + bRow) * N + bcol + bCol);
        __syncthreads();
        #pragma unroll
        for (int k = 0; k < 8; k++) {
            float ra[8], rb[8];
            *(float4*)(ra)     = *(const float4*)(&As[k][tr]);
            *(float4*)(ra + 4) = *(const float4*)(&As[k][tr + 4]);
            *(float4*)(rb)     = *(const float4*)(&Bs[k][tc]);
            *(float4*)(rb + 4) = *(const float4*)(&Bs[k][tc + 4]);
            #pragma unroll
            for (int i = 0; i < 8; i++)
                #pragma unroll
                for (int j = 0; j < 8; j++)
                    acc[i][j] += ra[i] * rb[j];
        }
        __syncthreads();
    }
    #pragma unroll
    for (int i = 0; i < 8; i++) {
        int gr = brow + tr + i;
        if (gr < M) {
            float4 v0 = make_float4(acc[i][0], acc[i][1], acc[i][2], acc[i][3]);
            float4 v1 = make_float4(acc[i][4], acc[i][5], acc[i][6], acc[i][7]);
            *(float4*)(C + (size_t)gr * N + bcol + tc)     = v0;
            *(float4*)(C + (size_t)gr * N + bcol + tc + 4) = v1;
        }
    }
}

// ---------------- BatchNorm stats (column mean/var over NN rows) ----------------
__global__ void k_bn_stats(const float* __restrict__ t, int C) {
    int c  = threadIdx.x;            // blockDim.x == C
    int r0 = blockIdx.x * 128;
    int r1 = min(NN, r0 + 128);
    float s = 0.f, q = 0.f;
    const float* p = t + (size_t)r0 * C + c;
    for (int r = r0; r < r1; r++, p += C) {
        float v = *p;
        s += v;
        q += v * v;
    }
    atomicAdd(&g_sum[c], (double)s);
    atomicAdd(&g_sq[c],  (double)q);
}

__global__ void k_bn_fin(int C) {
    int c = threadIdx.x;
    if (c >= C) return;
    double mu  = g_sum[c] / NN;
    double var = g_sq[c] / NN - mu * mu;
    if (var < 0.0) var = 0.0;
    g_mean[c] = (float)mu;
    g_rstd[c] = (float)rsqrt(var + 1e-5);
}

// out = relu(gamma*(in-mean)*rstd + beta); C is a power of two (cmask = C-1)
__global__ void k_bn_apply(const float* __restrict__ in, float* __restrict__ out,
                           const float* __restrict__ gg, const float* __restrict__ bb,
                           int cmask, long total) {
    long i  = blockIdx.x * (long)blockDim.x + threadIdx.x;
    long st = (long)gridDim.x * blockDim.x;
    for (; i < total; i += st) {
        int c   = (int)(i & cmask);
        float v = (in[i] - g_mean[c]) * g_rstd[c] * __ldg(&gg[c]) + __ldg(&bb[c]);
        out[i]  = v > 0.f ? v : 0.f;
    }
}

// ---------------- cosine losses (D = 128, one warp per node) ----------------
// useMask != 0: masked sum of (1-cos) into g_acc[accOff], count into g_acc[accOff+1]
// useMask == 0: sum over all nodes into g_acc[accOff]
__global__ void k_cos(const float* __restrict__ a, const float* __restrict__ b,
                      const void* __restrict__ m, int useMask, int accOff) {
    int gtid = blockIdx.x * blockDim.x + threadIdx.x;
    int warp = gtid >> 5, lane = gtid & 31;
    int nw   = (gridDim.x * blockDim.x) >> 5;
    double ls = 0.0, lc = 0.0;
    for (int n = warp; n < NN; n += nw) {
        if (useMask && !mask_at(m, n)) continue;   // warp-uniform
        float4 va = *((const float4*)(a + (size_t)n * 128) + lane);
        float4 vb = *((const float4*)(b + (size_t)n * 128) + lane);
        float dot = va.x * vb.x + va.y * vb.y + va.z * vb.z + va.w * vb.w;
        float na  = va.x * va.x + va.y * va.y + va.z * va.z + va.w * va.w;
        float nb  = vb.x * vb.x + vb.y * vb.y + vb.z * vb.z + vb.w * vb.w;
        #pragma unroll
        for (int o = 16; o; o >>= 1) {
            dot += __shfl_xor_sync(0xffffffffu, dot, o);
            na  += __shfl_xor_sync(0xffffffffu, na,  o);
            nb  += __shfl_xor_sync(0xffffffffu, nb,  o);
        }
        if (lane == 0) {
            float cs = dot / (fmaxf(sqrtf(na), 1e-12f) * fmaxf(sqrtf(nb), 1e-12f));
            ls += 1.0 - (double)cs;
            lc += 1.0;
        }
    }
    if (lane == 0) {
        atomicAdd(&g_acc[accOff], ls);
        if (useMask) atomicAdd(&g_acc[accOff + 1], lc);
    }
}

__global__ void k_finalize(float* out) {
    double v = g_acc[0] / g_acc[1] + g_acc[2] / g_acc[3] + 0.1 * (g_acc[4] / (double)NN);
    out[0] = (float)v;
}

// ---------------- host-side orchestration ----------------
static void run_layer(const float* in, int din, const void* ei,
                      const float* w1, const float* w2,
                      const float* bg, const float* bb,
                      const float* ng, const float* nb,
                      int dout, float* outbuf,
                      float* H, float* T, float* U) {
    long n4 = (long)NN * din / 4;
    k_copy4<<<4096, 256>>>((const float4*)in, (float4*)H, n4);
    k_scatter<<<40000, 256>>>(in, H, ei, din);

    dim3 g1(D_HID / 128, (NN + 127) / 128);
    k_sgemm<<<g1, 256>>>(H, w1, T, NN, din, D_HID);

    k_zero_stats<<<1, D_HID>>>(D_HID);
    k_bn_stats<<<(NN + 127) / 128, D_HID>>>(T, D_HID);
    k_bn_fin<<<1, D_HID>>>(D_HID);
    k_bn_apply<<<8192, 256>>>(T, T, bg, bb, D_HID - 1, (long)NN * D_HID);

    dim3 g2(dout / 128, (NN + 127) / 128);
    k_sgemm<<<g2, 256>>>(T, w2, U, NN, D_HID, dout);

    k_zero_stats<<<1, dout>>>(dout);
    k_bn_stats<<<(NN + 127) / 128, dout>>>(U, dout);
    k_bn_fin<<<1, dout>>>(dout);
    k_bn_apply<<<8192, 256>>>(U, outbuf, ng, nb, dout - 1, (long)NN * dout);
}

extern "C" void kernel_launch(void* const* d_in, const int* in_sizes, int n_in,
                              void* d_out, int out_size) {
    const float* x   = (const float*)d_in[0];
    const void*  ei1 = d_in[1];
    const void*  ei2 = d_in[2];
    const void*  m1  = d_in[3];
    const void*  m2  = d_in[4];
    // d_in[5] = batch : dead code in the reference (pooled outputs discarded)
    const float* e0_w1 = (const float*)d_in[6];
    const float* e0_w2 = (const float*)d_in[7];
    const float* e0_bg = (const float*)d_in[8];
    const float* e0_bb = (const float*)d_in[9];
    const float* e0_ng = (const float*)d_in[10];
    const float* e0_nb = (const float*)d_in[11];
    const float* e1_w1 = (const float*)d_in[12];
    const float* e1_w2 = (const float*)d_in[13];
    const float* e1_bg = (const float*)d_in[14];
    const float* e1_bb = (const float*)d_in[15];
    const float* e1_ng = (const float*)d_in[16];
    const float* e1_nb = (const float*)d_in[17];
    const float* d_w1  = (const float*)d_in[18];
    const float* d_w2  = (const float*)d_in[19];
    const float* d_bg  = (const float*)d_in[20];
    const float* d_bb  = (const float*)d_in[21];
    const float* d_ng  = (const float*)d_in[22];
    const float* d_nb  = (const float*)d_in[23];
    float* out = (float*)d_out;

    float *X1, *XN, *H, *T, *U, *RE1, *RE2;
    cudaGetSymbolAddress((void**)&X1,  g_X1);
    cudaGetSymbolAddress((void**)&XN,  g_XN);
    cudaGetSymbolAddress((void**)&H,   g_H);
    cudaGetSymbolAddress((void**)&T,   g_T);
    cudaGetSymbolAddress((void**)&U,   g_U);
    cudaGetSymbolAddress((void**)&RE1, g_RE1);
    cudaGetSymbolAddress((void**)&RE2, g_RE2);

    // dtype auto-detection (mask: u8/i32/f32, edges: i32/i64)
    k_zero_cnt<<<1, 32>>>();
    k_detect<<<128, 256>>>((const unsigned char*)m1, (const int*)ei1);
    k_detect_fin<<<1, 32>>>();

    k_zero_acc<<<1, 32>>>();

    for (int pass = 0; pass < 2; pass++) {
        const void* ei = pass == 0 ? ei1 : ei2;
        const void* m  = pass == 0 ? m1  : m2;
        float*      RE = pass == 0 ? RE1 : RE2;

        // x1 = where(mask, 0, x)
        k_mask<<<8192, 256>>>(x, m, X1, 7, (long)NN * D_IN);

        // encoder layer 0: 128 -> 256
        run_layer(X1, D_IN, ei, e0_w1, e0_w2, e0_bg, e0_bb, e0_ng, e0_nb,
                  D_OUT, XN, H, T, U);
        // encoder layer 1: 256 -> 256 (in-place safe: XN consumed before rewrite)
        run_layer(XN, D_OUT, ei, e1_w1, e1_w2, e1_bg, e1_bb, e1_ng, e1_nb,
                  D_OUT, XN, H, T, U);

        // re_h = where(mask, 0, h)
        k_mask<<<8192, 256>>>(XN, m, XN, 8, (long)NN * D_OUT);

        // decoder layer: 256 -> 128
        run_layer(XN, D_OUT, ei, d_w1, d_w2, d_bg, d_bb, d_ng, d_nb,
                  D_IN, RE, H, T, U);

        // masked reconstruction loss
        k_cos<<<512, 256>>>(RE, x, m, 1, pass * 2);
    }

    // contrastive term over all nodes
    k_cos<<<512, 256>>>(RE2, RE1, nullptr, 0, 4);
    k_finalize<<<1, 1>>>(out);
    (void)in_sizes; (void)n_in; (void)out_size;
}

// round 3
// speedup vs baseline: 1.9329x; 1.9329x over previous
#include <cuda_runtime.h>
#include <math.h>
#include <stdint.h>

#define NN    50000
#define NE    320000
#define D_IN  128
#define D_OUT 256
#define D_HID 512

// ---------------- scratch (static device globals; no allocation) ----------------
__device__ float  g_X1 [(size_t)NN * D_IN];
__device__ float  g_XN [(size_t)NN * D_OUT];
__device__ float  g_H  [(size_t)NN * D_OUT];
__device__ float  g_T  [(size_t)NN * D_HID];
__device__ float  g_U  [(size_t)NN * D_OUT];
__device__ float  g_RE1[(size_t)NN * D_IN];
__device__ float  g_RE2[(size_t)NN * D_IN];
__device__ double g_sum[D_HID];
__device__ double g_sq [D_HID];
__device__ float  g_mean[D_HID];
__device__ float  g_rstd[D_HID];
__device__ double g_acc[8]; // [0]=sum1 [1]=cnt1 [2]=sum2 [3]=cnt2 [4]=cl_sum

// dtype-detection flags + counters
__device__ int g_mask_mode;   // 0 = uint8, 1 = int32, 2 = float32
__device__ int g_ei_i64;      // 0 = int32, 1 = int64
__device__ int g_cnt[8];      // scratch counters

// ---------------- dtype detection ----------------
__global__ void k_zero_cnt() { if (threadIdx.x < 8) g_cnt[threadIdx.x] = 0; }

__global__ void k_detect(const unsigned char* __restrict__ mbytes,
                         const int* __restrict__ eints) {
    int i  = blockIdx.x * blockDim.x + threadIdx.x;
    int st = gridDim.x * blockDim.x;
    int c1 = 0, c3 = 0, ez = 0;
    for (int j = i; j < NN; j += st) {
        unsigned char v = mbytes[j];
        if (v && (j & 3) == 1) c1++;
        if (v && (j & 3) == 3) c3++;
    }
    for (int j = i; j < 100000; j += st)
        if ((j & 1) && eints[j] == 0) ez++;
    atomicAdd(&g_cnt[0], c1);
    atomicAdd(&g_cnt[1], c3);
    atomicAdd(&g_cnt[2], ez);
}

__global__ void k_detect_fin() {
    if (threadIdx.x == 0) {
        if      (g_cnt[1] > 1000) g_mask_mode = 2;
        else if (g_cnt[0] > 1000) g_mask_mode = 0;
        else                      g_mask_mode = 1;
        g_ei_i64 = (g_cnt[2] > 25000) ? 1 : 0;
    }
}

__device__ __forceinline__ bool mask_at(const void* __restrict__ m, int n) {
    int mode = g_mask_mode;
    if (mode == 0) return ((const unsigned char*)m)[n] != 0;
    if (mode == 1) return ((const int*)m)[n] != 0;
    return ((const float*)m)[n] != 0.f;
}

__device__ __forceinline__ int ei_at(const void* __restrict__ ei, long idx) {
    return g_ei_i64 ? (int)((const long long*)ei)[idx] : ((const int*)ei)[idx];
}

// ---------------- tiny utility kernels ----------------
__global__ void k_zero_acc() {
    if (threadIdx.x < 8) g_acc[threadIdx.x] = 0.0;
}

__global__ void k_zero_stats(int C) {
    int c = threadIdx.x;
    if (c < C) { g_sum[c] = 0.0; g_sq[c] = 0.0; }
}

__global__ void k_mask(const float* __restrict__ in, const void* __restrict__ m,
                       float* __restrict__ out, int dshift, long total) {
    long i  = blockIdx.x * (long)blockDim.x + threadIdx.x;
    long st = (long)gridDim.x * blockDim.x;
    for (; i < total; i += st) {
        int node = (int)(i >> dshift);
        out[i] = mask_at(m, node) ? 0.f : in[i];
    }
}

__global__ void k_copy4(const float4* __restrict__ src, float4* __restrict__ dst, long n4) {
    long i  = blockIdx.x * (long)blockDim.x + threadIdx.x;
    long st = (long)gridDim.x * blockDim.x;
    for (; i < n4; i += st) dst[i] = src[i];
}

// ---------------- edge scatter: h[dst] += xn[src], one warp per edge ----------------
__global__ void k_scatter(const float* __restrict__ xn, float* __restrict__ h,
                          const void* __restrict__ ei, int D) {
    int gtid = blockIdx.x * blockDim.x + threadIdx.x;
    int warp = gtid >> 5, lane = gtid & 31;
    int nw   = (gridDim.x * blockDim.x) >> 5;
    for (int e = warp; e < NE; e += nw) {
        int s = ei_at(ei, e);
        int d = ei_at(ei, (long)NE + e);
        const float* sp = xn + (size_t)s * D;
        float*       dp = h  + (size_t)d * D;
        for (int c = lane; c < D; c += 32)
            atomicAdd(&dp[c], __ldg(&sp[c]));
    }
}

// ---------------- TF32 tensor-core GEMM ----------------
// C[MxN] = A[MxK] @ B[KxN], row-major fp32 in/out, tf32 mma with fp32 accumulate.
// 128x128x16 CTA tile, 256 threads = 8 warps in 4x2 (m x n), warp tile 32x64.
// Requires K % 16 == 0, N % 128 == 0 (true for all shapes here); M ragged.
__device__ __forceinline__ uint32_t f2tf32(float f) {
    uint32_t r;
    asm("cvt.rna.tf32.f32 %0, %1;" : "=r"(r) : "f"(f));
    return r;
}

__device__ __forceinline__ void mma_tf32(float* d, const uint32_t* a, const uint32_t* b) {
    asm volatile(
        "mma.sync.aligned.m16n8k8.row.col.f32.tf32.tf32.f32 "
        "{%0,%1,%2,%3}, {%4,%5,%6,%7}, {%8,%9}, {%0,%1,%2,%3};"
        : "+f"(d[0]), "+f"(d[1]), "+f"(d[2]), "+f"(d[3])
        : "r"(a[0]), "r"(a[1]), "r"(a[2]), "r"(a[3]), "r"(b[0]), "r"(b[1]));
}

__global__ void __launch_bounds__(256)
k_gemm_tf32(const float* __restrict__ A, const float* __restrict__ B,
            float* __restrict__ C, int M, int K, int N) {
    __shared__ uint32_t As[128][20];   // [m][k], pad 4 -> stride 20 (conflict-free frags)
    __shared__ uint32_t Bs[16][136];   // [k][n], pad 8 -> stride 136

    const int tid  = threadIdx.x;
    const int lane = tid & 31;
    const int warp = tid >> 5;
    const int wm   = warp & 3;         // 4 warps along M (32 rows each)
    const int wn   = warp >> 2;        // 2 warps along N (64 cols each)
    const int gid  = lane >> 2;        // 0..7
    const int tq   = lane & 3;         // 0..3
    const int brow = blockIdx.y * 128;
    const int bcol = blockIdx.x * 128;

    float acc[2][8][4];
    #pragma unroll
    for (int i = 0; i < 2; i++)
        #pragma unroll
        for (int j = 0; j < 8; j++)
            #pragma unroll
            for (int q = 0; q < 4; q++) acc[i][j][q] = 0.f;

    for (int k0 = 0; k0 < K; k0 += 16) {
        // A tile: 128 rows x 16 cols, 512 float4 loads over 256 threads x 2
        #pragma unroll
        for (int i = 0; i < 2; i++) {
            int idx = tid + i * 256;
            int row = idx >> 2;
            int c4  = (idx & 3) << 2;
            float4 v = make_float4(0.f, 0.f, 0.f, 0.f);
            if (brow + row < M)
                v = *(const float4*)(A + (size_t)(brow + row) * K + k0 + c4);
            As[row][c4 + 0] = f2tf32(v.x);
            As[row][c4 + 1] = f2tf32(v.y);
            As[row][c4 + 2] = f2tf32(v.z);
            As[row][c4 + 3] = f2tf32(v.w);
        }
        // B tile: 16 rows x 128 cols
        #pragma unroll
        for (int i = 0; i < 2; i++) {
            int idx = tid + i * 256;
            int kr = idx >> 5;
            int nc = (idx & 31) << 2;
            float4 v = *(const float4*)(B + (size_t)(k0 + kr) * N + bcol + nc);
            Bs[kr][nc + 0] = f2tf32(v.x);
            Bs[kr][nc + 1] = f2tf32(v.y);
            Bs[kr][nc + 2] = f2tf32(v.z);
            Bs[kr][nc + 3] = f2tf32(v.w);
        }
        __syncthreads();

        #pragma unroll
        for (int kk = 0; kk < 16; kk += 8) {
            uint32_t a[2][4], b[8][2];
            #pragma unroll
            for (int mt = 0; mt < 2; mt++) {
                int r = wm * 32 + mt * 16 + gid;
                a[mt][0] = As[r][kk + tq];
                a[mt][1] = As[r + 8][kk + tq];
                a[mt][2] = As[r][kk + tq + 4];
                a[mt][3] = As[r + 8][kk + tq + 4];
            }
            #pragma unroll
            for (int nt = 0; nt < 8; nt++) {
                int cn = wn * 64 + nt * 8 + gid;
                b[nt][0] = Bs[kk + tq][cn];
                b[nt][1] = Bs[kk + tq + 4][cn];
            }
            #pragma unroll
            for (int mt = 0; mt < 2; mt++)
                #pragma unroll
                for (int nt = 0; nt < 8; nt++)
                    mma_tf32(acc[mt][nt], a[mt], b[nt]);
        }
        __syncthreads();
    }

    // epilogue: each thread owns cols (2tq, 2tq+1) at rows (gid, gid+8) per tile
    #pragma unroll
    for (int mt = 0; mt < 2; mt++) {
        int r0 = brow + wm * 32 + mt * 16 + gid;
        int r1 = r0 + 8;
        #pragma unroll
        for (int nt = 0; nt < 8; nt++) {
            int c = bcol + wn * 64 + nt * 8 + tq * 2;
            if (r0 < M)
                *(float2*)(C + (size_t)r0 * N + c) = make_float2(acc[mt][nt][0], acc[mt][nt][1]);
            if (r1 < M)
                *(float2*)(C + (size_t)r1 * N + c) = make_float2(acc[mt][nt][2], acc[mt][nt][3]);
        }
    }
}

// ---------------- BatchNorm stats (column mean/var over NN rows) ----------------
__global__ void k_bn_stats(const float* __restrict__ t, int C) {
    int c  = threadIdx.x;            // blockDim.x == C
    int r0 = blockIdx.x * 128;
    int r1 = min(NN, r0 + 128);
    float s = 0.f, q = 0.f;
    const float* p = t + (size_t)r0 * C + c;
    for (int r = r0; r < r1; r++, p += C) {
        float v = *p;
        s += v;
        q += v * v;
    }
    atomicAdd(&g_sum[c], (double)s);
    atomicAdd(&g_sq[c],  (double)q);
}

__global__ void k_bn_fin(int C) {
    int c = threadIdx.x;
    if (c >= C) return;
    double mu  = g_sum[c] / NN;
    double var = g_sq[c] / NN - mu * mu;
    if (var < 0.0) var = 0.0;
    g_mean[c] = (float)mu;
    g_rstd[c] = (float)rsqrt(var + 1e-5);
}

__global__ void k_bn_apply(const float* __restrict__ in, float* __restrict__ out,
                           const float* __restrict__ gg, const float* __restrict__ bb,
                           int cmask, long total) {
    long i  = blockIdx.x * (long)blockDim.x + threadIdx.x;
    long st = (long)gridDim.x * blockDim.x;
    for (; i < total; i += st) {
        int c   = (int)(i & cmask);
        float v = (in[i] - g_mean[c]) * g_rstd[c] * __ldg(&gg[c]) + __ldg(&bb[c]);
        out[i]  = v > 0.f ? v : 0.f;
    }
}

// ---------------- cosine losses (D = 128, one warp per node) ----------------
__global__ void k_cos(const float* __restrict__ a, const float* __restrict__ b,
                      const void* __restrict__ m, int useMask, int accOff) {
    int gtid = blockIdx.x * blockDim.x + threadIdx.x;
    int warp = gtid >> 5, lane = gtid & 31;
    int nw   = (gridDim.x * blockDim.x) >> 5;
    double ls = 0.0, lc = 0.0;
    for (int n = warp; n < NN; n += nw) {
        if (useMask && !mask_at(m, n)) continue;   // warp-uniform
        float4 va = *((const float4*)(a + (size_t)n * 128) + lane);
        float4 vb = *((const float4*)(b + (size_t)n * 128) + lane);
        float dot = va.x * vb.x + va.y * vb.y + va.z * vb.z + va.w * vb.w;
        float na  = va.x * va.x + va.y * va.y + va.z * va.z + va.w * va.w;
        float nb  = vb.x * vb.x + vb.y * vb.y + vb.z * vb.z + vb.w * vb.w;
        #pragma unroll
        for (int o = 16; o; o >>= 1) {
            dot += __shfl_xor_sync(0xffffffffu, dot, o);
            na  += __shfl_xor_sync(0xffffffffu, na,  o);
            nb  += __shfl_xor_sync(0xffffffffu, nb,  o);
        }
        if (lane == 0) {
            float cs = dot / (fmaxf(sqrtf(na), 1e-12f) * fmaxf(sqrtf(nb), 1e-12f));
            ls += 1.0 - (double)cs;
            lc += 1.0;
        }
    }
    if (lane == 0) {
        atomicAdd(&g_acc[accOff], ls);
        if (useMask) atomicAdd(&g_acc[accOff + 1], lc);
    }
}

__global__ void k_finalize(float* out) {
    double v = g_acc[0] / g_acc[1] + g_acc[2] / g_acc[3] + 0.1 * (g_acc[4] / (double)NN);
    out[0] = (float)v;
}

// ---------------- host-side orchestration ----------------
static void run_layer(const float* in, int din, const void* ei,
                      const float* w1, const float* w2,
                      const float* bg, const float* bb,
                      const float* ng, const float* nb,
                      int dout, float* outbuf,
                      float* H, float* T, float* U) {
    long n4 = (long)NN * din / 4;
    k_copy4<<<4096, 256>>>((const float4*)in, (float4*)H, n4);
    k_scatter<<<40000, 256>>>(in, H, ei, din);

    dim3 g1(D_HID / 128, (NN + 127) / 128);
    k_gemm_tf32<<<g1, 256>>>(H, w1, T, NN, din, D_HID);

    k_zero_stats<<<1, D_HID>>>(D_HID);
    k_bn_stats<<<(NN + 127) / 128, D_HID>>>(T, D_HID);
    k_bn_fin<<<1, D_HID>>>(D_HID);
    k_bn_apply<<<8192, 256>>>(T, T, bg, bb, D_HID - 1, (long)NN * D_HID);

    dim3 g2(dout / 128, (NN + 127) / 128);
    k_gemm_tf32<<<g2, 256>>>(T, w2, U, NN, D_HID, dout);

    k_zero_stats<<<1, dout>>>(dout);
    k_bn_stats<<<(NN + 127) / 128, dout>>>(U, dout);
    k_bn_fin<<<1, dout>>>(dout);
    k_bn_apply<<<8192, 256>>>(U, outbuf, ng, nb, dout - 1, (long)NN * dout);
}

extern "C" void kernel_launch(void* const* d_in, const int* in_sizes, int n_in,
                              void* d_out, int out_size) {
    const float* x   = (const float*)d_in[0];
    const void*  ei1 = d_in[1];
    const void*  ei2 = d_in[2];
    const void*  m1  = d_in[3];
    const void*  m2  = d_in[4];
    // d_in[5] = batch : dead code in the reference (pooled outputs discarded)
    const float* e0_w1 = (const float*)d_in[6];
    const float* e0_w2 = (const float*)d_in[7];
    const float* e0_bg = (const float*)d_in[8];
    const float* e0_bb = (const float*)d_in[9];
    const float* e0_ng = (const float*)d_in[10];
    const float* e0_nb = (const float*)d_in[11];
    const float* e1_w1 = (const float*)d_in[12];
    const float* e1_w2 = (const float*)d_in[13];
    const float* e1_bg = (const float*)d_in[14];
    const float* e1_bb = (const float*)d_in[15];
    const float* e1_ng = (const float*)d_in[16];
    const float* e1_nb = (const float*)d_in[17];
    const float* d_w1  = (const float*)d_in[18];
    const float* d_w2  = (const float*)d_in[19];
    const float* d_bg  = (const float*)d_in[20];
    const float* d_bb  = (const float*)d_in[21];
    const float* d_ng  = (const float*)d_in[22];
    const float* d_nb  = (const float*)d_in[23];
    float* out = (float*)d_out;

    float *X1, *XN, *H, *T, *U, *RE1, *RE2;
    cudaGetSymbolAddress((void**)&X1,  g_X1);
    cudaGetSymbolAddress((void**)&XN,  g_XN);
    cudaGetSymbolAddress((void**)&H,   g_H);
    cudaGetSymbolAddress((void**)&T,   g_T);
    cudaGetSymbolAddress((void**)&U,   g_U);
    cudaGetSymbolAddress((void**)&RE1, g_RE1);
    cudaGetSymbolAddress((void**)&RE2, g_RE2);

    // dtype auto-detection (mask: u8/i32/f32, edges: i32/i64)
    k_zero_cnt<<<1, 32>>>();
    k_detect<<<128, 256>>>((const unsigned char*)m1, (const int*)ei1);
    k_detect_fin<<<1, 32>>>();

    k_zero_acc<<<1, 32>>>();

    for (int pass = 0; pass < 2; pass++) {
        const void* ei = pass == 0 ? ei1 : ei2;
        const void* m  = pass == 0 ? m1  : m2;
        float*      RE = pass == 0 ? RE1 : RE2;

        // x1 = where(mask, 0, x)
        k_mask<<<8192, 256>>>(x, m, X1, 7, (long)NN * D_IN);

        // encoder layer 0: 128 -> 256
        run_layer(X1, D_IN, ei, e0_w1, e0_w2, e0_bg, e0_bb, e0_ng, e0_nb,
                  D_OUT, XN, H, T, U);
        // encoder layer 1: 256 -> 256
        run_layer(XN, D_OUT, ei, e1_w1, e1_w2, e1_bg, e1_bb, e1_ng, e1_nb,
                  D_OUT, XN, H, T, U);

        // re_h = where(mask, 0, h)
        k_mask<<<8192, 256>>>(XN, m, XN, 8, (long)NN * D_OUT);

        // decoder layer: 256 -> 128
        run_layer(XN, D_OUT, ei, d_w1, d_w2, d_bg, d_bb, d_ng, d_nb,
                  D_IN, RE, H, T, U);

        // masked reconstruction loss
        k_cos<<<512, 256>>>(RE, x, m, 1, pass * 2);
    }

    // contrastive term over all nodes
    k_cos<<<512, 256>>>(RE2, RE1, nullptr, 0, 4);
    k_finalize<<<1, 1>>>(out);
    (void)in_sizes; (void)n_in; (void)out_size;
}